// round 2
// baseline (speedup 1.0000x reference)
#include <cuda_runtime.h>
#include <math.h>
#include <stdint.h>

#define TT 1024
#define BB 64
#define NIN 128
#define NHID 512
#define WLD (NHID + NIN + 1)   // 641, w_rec row stride

// scratch: precomputed input projection xin[t][b][h]  (128 MB, static device array)
__device__ float g_xin[(size_t)TT * BB * NHID];
// grid barrier counter (monotonic within one launch, zeroed by zero kernel each launch)
__device__ unsigned int g_bar;

__global__ void zero_bar_kernel() { g_bar = 0u; }

// ---------------------------------------------------------------------------
// Kernel 1: xin[m][n] = sum_i x[m][i] * w_x[n][i] + bias[n]
//   m = t*B+b in [0,65536), n = h in [0,512), K = 128
//   64x64 tile per block, 256 threads, 4x4 micro-tile, K staged fully in smem.
// ---------------------------------------------------------------------------
__global__ __launch_bounds__(256) void precompute_kernel(
    const float* __restrict__ x, const float* __restrict__ w_rec) {
  extern __shared__ float sm[];
  float* xs = sm;                    // [64][132]  (m-major, padded)
  float* ws = sm + 64 * 132;         // [128][68]  (k-major, padded)
  float* bs = ws + 128 * 68;         // [64]

  const int m0 = blockIdx.x * 64;
  const int n0 = blockIdx.y * 64;
  const int tid = threadIdx.x;

  // load x tile (rows are contiguous 128-float rows -> float4)
  const float4* xg = (const float4*)(x + (size_t)m0 * NIN);
  for (int i = tid; i < 64 * 32; i += 256) {
    int r = i >> 5, c4 = i & 31;
    float4 v = xg[r * 32 + c4];
    *(float4*)&xs[r * 132 + c4 * 4] = v;
  }
  // load w_x tile, transposed to k-major (scalar: w_rec rows are stride-641, misaligned)
  for (int i = tid; i < 64 * 128; i += 256) {
    int h = i >> 7, k = i & 127;
    ws[k * 68 + h] = w_rec[(size_t)(n0 + h) * WLD + NHID + k];
  }
  if (tid < 64) bs[tid] = w_rec[(size_t)(n0 + tid) * WLD + NHID + NIN];
  __syncthreads();

  const int ty = tid >> 4;   // 0..15 (m micro-rows *4)
  const int tx = tid & 15;   // 0..15 (n micro-cols *4)

  float acc[4][4];
#pragma unroll
  for (int u = 0; u < 4; u++)
#pragma unroll
    for (int v = 0; v < 4; v++) acc[u][v] = 0.0f;

  const float* xr0 = &xs[(ty * 4 + 0) * 132];
  const float* xr1 = &xs[(ty * 4 + 1) * 132];
  const float* xr2 = &xs[(ty * 4 + 2) * 132];
  const float* xr3 = &xs[(ty * 4 + 3) * 132];

#pragma unroll 4
  for (int k = 0; k < 128; k++) {
    float a0 = xr0[k], a1 = xr1[k], a2 = xr2[k], a3 = xr3[k];
    float4 bv = *(const float4*)&ws[k * 68 + tx * 4];
    acc[0][0] += a0 * bv.x; acc[0][1] += a0 * bv.y; acc[0][2] += a0 * bv.z; acc[0][3] += a0 * bv.w;
    acc[1][0] += a1 * bv.x; acc[1][1] += a1 * bv.y; acc[1][2] += a1 * bv.z; acc[1][3] += a1 * bv.w;
    acc[2][0] += a2 * bv.x; acc[2][1] += a2 * bv.y; acc[2][2] += a2 * bv.z; acc[2][3] += a2 * bv.w;
    acc[3][0] += a3 * bv.x; acc[3][1] += a3 * bv.y; acc[3][2] += a3 * bv.z; acc[3][3] += a3 * bv.w;
  }

  float4 bias4 = *(const float4*)&bs[tx * 4];
#pragma unroll
  for (int u = 0; u < 4; u++) {
    float4 r;
    r.x = acc[u][0] + bias4.x;
    r.y = acc[u][1] + bias4.y;
    r.z = acc[u][2] + bias4.z;
    r.w = acc[u][3] + bias4.w;
    *(float4*)&g_xin[(size_t)(m0 + ty * 4 + u) * NHID + n0 + tx * 4] = r;
  }
}

// ---------------------------------------------------------------------------
// Kernel 2: persistent recurrence.
//   64 blocks x 64 threads. Block (bh,bb) owns h-slice [bh*32, bh*32+32) for
//   batch slice [bb*16, bb*16+16). w_h slice lives in SMEM for all 1024 steps.
//   Per step: stage h_prev slice (from d_out[t-1] / h0), 4x2 register micro
//   over K=512, + xin, tanh, write d_out[t], grid barrier.
// ---------------------------------------------------------------------------
__global__ __launch_bounds__(64, 1) void rnn_rec_kernel(
    const float* __restrict__ h0, const float* __restrict__ w_rec,
    float* __restrict__ out) {
  extern __shared__ float sm[];
  float* Ws = sm;                 // [32][513]
  float* hs = sm + 32 * 513;      // [16][516]

  const int tid = threadIdx.x;
  const int bh = blockIdx.x & 15;   // 16 h-groups of 32
  const int bb = blockIdx.x >> 4;   // 4 b-groups of 16
  const int hblk = bh * 32;
  const int b0 = bb * 16;

  // load persistent w_h slice (scalar; w_rec rows misaligned for float4)
  for (int i = tid; i < 32 * 512; i += 64) {
    int r = i >> 9, c = i & 511;
    Ws[r * 513 + c] = w_rec[(size_t)(hblk + r) * WLD + c];
  }

  const int th = tid & 7;    // h micro group (4 rows)
  const int tb = tid >> 3;   // b micro group (2 rows)
  const int hb = hblk + th * 4;
  const int bA = b0 + tb * 2;

  const float* wr0 = &Ws[(th * 4 + 0) * 513];
  const float* wr1 = &Ws[(th * 4 + 1) * 513];
  const float* wr2 = &Ws[(th * 4 + 2) * 513];
  const float* wr3 = &Ws[(th * 4 + 3) * 513];
  const float* hr0 = &hs[(tb * 2 + 0) * 516];
  const float* hr1 = &hs[(tb * 2 + 1) * 516];

  __syncthreads();

  for (int t = 0; t < TT; t++) {
    const float* hp = (t == 0) ? h0 : (out + (size_t)(t - 1) * BB * NHID);
    // stage h_prev slice (L2 via ldcg; rows are 512-float aligned -> float4)
    for (int i = tid; i < 16 * 128; i += 64) {
      int r = i >> 7, c4 = i & 127;
      float4 v = __ldcg((const float4*)(hp + (size_t)(b0 + r) * NHID + c4 * 4));
      *(float4*)&hs[r * 516 + c4 * 4] = v;
    }
    __syncthreads();

    float a00 = 0.f, a01 = 0.f, a10 = 0.f, a11 = 0.f;
    float a20 = 0.f, a21 = 0.f, a30 = 0.f, a31 = 0.f;
#pragma unroll 8
    for (int k = 0; k < 512; k++) {
      float w0 = wr0[k], w1 = wr1[k], w2 = wr2[k], w3 = wr3[k];
      float hv0 = hr0[k], hv1 = hr1[k];
      a00 += w0 * hv0; a01 += w0 * hv1;
      a10 += w1 * hv0; a11 += w1 * hv1;
      a20 += w2 * hv0; a21 += w2 * hv1;
      a30 += w3 * hv0; a31 += w3 * hv1;
    }

    // epilogue: + xin, tanh, store to out[t]
    const float* urow = g_xin + (size_t)t * BB * NHID;
    float* orow = out + (size_t)t * BB * NHID;
    {
      float4 u0 = *(const float4*)(urow + (size_t)bA * NHID + hb);
      float4 r0;
      r0.x = tanhf(a00 + u0.x);
      r0.y = tanhf(a10 + u0.y);
      r0.z = tanhf(a20 + u0.z);
      r0.w = tanhf(a30 + u0.w);
      *(float4*)(orow + (size_t)bA * NHID + hb) = r0;

      float4 u1 = *(const float4*)(urow + (size_t)(bA + 1) * NHID + hb);
      float4 r1;
      r1.x = tanhf(a01 + u1.x);
      r1.y = tanhf(a11 + u1.y);
      r1.z = tanhf(a21 + u1.z);
      r1.w = tanhf(a31 + u1.w);
      *(float4*)(orow + (size_t)(bA + 1) * NHID + hb) = r1;
    }

    // grid barrier: all 64 blocks must finish step t before any reads out[t]
    __syncthreads();
    __threadfence();
    if (tid == 0) {
      atomicAdd(&g_bar, 1u);
      const unsigned int target = 64u * (unsigned)(t + 1);
      while (*((volatile unsigned int*)&g_bar) < target) {
        __nanosleep(40);
      }
    }
    __syncthreads();
  }
}

// ---------------------------------------------------------------------------
extern "C" void kernel_launch(void* const* d_in, const int* in_sizes, int n_in,
                              void* d_out, int out_size) {
  const float* x     = (const float*)d_in[0];  // (T,B,NIN) f32
  const float* h0    = (const float*)d_in[1];  // (B,NH)    f32
  const float* w_rec = (const float*)d_in[2];  // (NH, NH+NIN+1) f32
  float* out = (float*)d_out;                  // (T,B,NH)  f32

  const int pre_smem = (64 * 132 + 128 * 68 + 64) * (int)sizeof(float);   // 68864 B
  const int rec_smem = (32 * 513 + 16 * 516) * (int)sizeof(float);        // 98688 B
  cudaFuncSetAttribute(precompute_kernel,
                       cudaFuncAttributeMaxDynamicSharedMemorySize, pre_smem);
  cudaFuncSetAttribute(rnn_rec_kernel,
                       cudaFuncAttributeMaxDynamicSharedMemorySize, rec_smem);

  zero_bar_kernel<<<1, 1>>>();

  dim3 pgrid(TT * BB / 64, NHID / 64);  // 1024 x 8
  precompute_kernel<<<pgrid, 256, pre_smem>>>(x, w_rec);

  rnn_rec_kernel<<<64, 64, rec_smem>>>(h0, w_rec, out);
}

// round 3
// speedup vs baseline: 1.8985x; 1.8985x over previous
#include <cuda_runtime.h>
#include <math.h>
#include <stdint.h>

#define TT 1024
#define BB 64
#define NIN 128
#define NHID 512
#define WLD (NHID + NIN + 1)   // 641, w_rec row stride

// scratch: precomputed input projection xin[t][b][h]  (128 MB, static device array)
__device__ float g_xin[(size_t)TT * BB * NHID];
// grid barrier counter (monotonic within one launch, zeroed each launch)
__device__ unsigned int g_bar;

__global__ void zero_bar_kernel() { g_bar = 0u; }

// ---------------------------------------------------------------------------
// Kernel 1: xin[m][n] = sum_i x[m][i] * w_x[n][i] + bias[n]
//   m = t*B+b in [0,65536), n = h in [0,512), K = 128
//   64x64 tile per block, 256 threads, 4x4 micro-tile, K staged fully in smem.
// ---------------------------------------------------------------------------
__global__ __launch_bounds__(256) void precompute_kernel(
    const float* __restrict__ x, const float* __restrict__ w_rec) {
  extern __shared__ float sm[];
  float* xs = sm;                    // [64][132]  (m-major, padded)
  float* ws = sm + 64 * 132;         // [128][68]  (k-major, padded)
  float* bs = ws + 128 * 68;         // [64]

  const int m0 = blockIdx.x * 64;
  const int n0 = blockIdx.y * 64;
  const int tid = threadIdx.x;

  const float4* xg = (const float4*)(x + (size_t)m0 * NIN);
  for (int i = tid; i < 64 * 32; i += 256) {
    int r = i >> 5, c4 = i & 31;
    float4 v = xg[r * 32 + c4];
    *(float4*)&xs[r * 132 + c4 * 4] = v;
  }
  for (int i = tid; i < 64 * 128; i += 256) {
    int h = i >> 7, k = i & 127;
    ws[k * 68 + h] = w_rec[(size_t)(n0 + h) * WLD + NHID + k];
  }
  if (tid < 64) bs[tid] = w_rec[(size_t)(n0 + tid) * WLD + NHID + NIN];
  __syncthreads();

  const int ty = tid >> 4;
  const int tx = tid & 15;

  float acc[4][4];
#pragma unroll
  for (int u = 0; u < 4; u++)
#pragma unroll
    for (int v = 0; v < 4; v++) acc[u][v] = 0.0f;

  const float* xr0 = &xs[(ty * 4 + 0) * 132];
  const float* xr1 = &xs[(ty * 4 + 1) * 132];
  const float* xr2 = &xs[(ty * 4 + 2) * 132];
  const float* xr3 = &xs[(ty * 4 + 3) * 132];

#pragma unroll 4
  for (int k = 0; k < 128; k++) {
    float a0 = xr0[k], a1 = xr1[k], a2 = xr2[k], a3 = xr3[k];
    float4 bv = *(const float4*)&ws[k * 68 + tx * 4];
    acc[0][0] += a0 * bv.x; acc[0][1] += a0 * bv.y; acc[0][2] += a0 * bv.z; acc[0][3] += a0 * bv.w;
    acc[1][0] += a1 * bv.x; acc[1][1] += a1 * bv.y; acc[1][2] += a1 * bv.z; acc[1][3] += a1 * bv.w;
    acc[2][0] += a2 * bv.x; acc[2][1] += a2 * bv.y; acc[2][2] += a2 * bv.z; acc[2][3] += a2 * bv.w;
    acc[3][0] += a3 * bv.x; acc[3][1] += a3 * bv.y; acc[3][2] += a3 * bv.z; acc[3][3] += a3 * bv.w;
  }

  float4 bias4 = *(const float4*)&bs[tx * 4];
#pragma unroll
  for (int u = 0; u < 4; u++) {
    float4 r;
    r.x = acc[u][0] + bias4.x;
    r.y = acc[u][1] + bias4.y;
    r.z = acc[u][2] + bias4.z;
    r.w = acc[u][3] + bias4.w;
    *(float4*)&g_xin[(size_t)(m0 + ty * 4 + u) * NHID + n0 + tx * 4] = r;
  }
}

// ---------------------------------------------------------------------------
// Kernel 2: persistent recurrence, v2.
//   128 blocks x 256 threads. Block (bhg,bbg) owns h-slice [bhg*16,+16) for
//   batch slice [bbg*16,+16). w_h slice lives in REGISTERS (constant over t):
//   thread = (4h x 8b) micro x K-split-32 (k = kq mod 32, interleaved).
//   Per step: stage h k-major into smem, 2 LDS.128 + 32 FFMA per k-iter,
//   smem reduce of 32 K-partials, fused xin+tanh epilogue, grid barrier.
// ---------------------------------------------------------------------------
#define HS_STRIDE 36      // floats per k-row: b0..7 at +0, b8..15 at +16 (gap kills conflicts)
#define RED_STRIDE 260    // floats per kq-row of the reduction buffer

__global__ __launch_bounds__(256, 1) void rnn_rec_kernel(
    const float* __restrict__ h0, const float* __restrict__ w_rec,
    float* __restrict__ out) {
  extern __shared__ float sm[];
  float* hs  = sm;                        // [512][HS_STRIDE]
  float* red = sm + 512 * HS_STRIDE;      // [32][RED_STRIDE]

  const int tid = threadIdx.x;
  const int bhg = blockIdx.x & 31;   // 32 h-groups of 16 rows
  const int bbg = blockIdx.x >> 5;   // 4 b-groups of 16
  const int hblk = bhg * 16;
  const int b0 = bbg * 16;

  const int th = tid & 3;            // 4 h-subgroups of 4 rows
  const int tb = (tid >> 2) & 1;     // 2 batch halves of 8
  const int kq = tid >> 3;           // 0..31, k = kq + 32*i

  // persistent W registers: rows hblk + th*4 + j, k = kq + 32*i
  float Wreg[4][16];
#pragma unroll
  for (int j = 0; j < 4; j++) {
    const float* wrow = w_rec + (size_t)(hblk + th * 4 + j) * WLD + kq;
#pragma unroll
    for (int i = 0; i < 16; i++) Wreg[j][i] = wrow[i * 32];
  }

  // h staging assignment: lane covers one batch row x 32 consecutive k
  const int st_bl = tid & 15;                         // batch row 0..15
  const int st_kc = tid >> 4;                         // k chunk 0..15 (32 k each)
  const int st_boff = (st_bl & 8) ? (st_bl + 8) : st_bl;  // split layout col

  // reduce/epilogue output index: o_h fastest -> coalesced gmem access
  const int o_h = tid & 15;
  const int o_b = tid >> 4;

  const int tbofs = 16 * tb;

  for (int t = 0; t < TT; t++) {
    const float* hp = (t == 0) ? h0 : (out + (size_t)(t - 1) * BB * NHID);

    // stage h slice: gmem (b-major) -> smem (k-major split layout)
    const float* src = hp + (size_t)(b0 + st_bl) * NHID + st_kc * 32;
#pragma unroll
    for (int m4 = 0; m4 < 8; m4++) {
      float4 v = __ldcg((const float4*)(src + m4 * 4));
      int kb = st_kc * 32 + m4 * 4;
      hs[(kb + 0) * HS_STRIDE + st_boff] = v.x;
      hs[(kb + 1) * HS_STRIDE + st_boff] = v.y;
      hs[(kb + 2) * HS_STRIDE + st_boff] = v.z;
      hs[(kb + 3) * HS_STRIDE + st_boff] = v.w;
    }
    __syncthreads();

    float acc[4][8];
#pragma unroll
    for (int j = 0; j < 4; j++)
#pragma unroll
      for (int b = 0; b < 8; b++) acc[j][b] = 0.0f;

#pragma unroll
    for (int i = 0; i < 16; i++) {
      const int k = kq + 32 * i;
      const float* hrow = &hs[k * HS_STRIDE + tbofs];
      float4 lo = *(const float4*)(hrow);
      float4 hi = *(const float4*)(hrow + 4);
      float hb0 = lo.x, hb1 = lo.y, hb2 = lo.z, hb3 = lo.w;
      float hb4 = hi.x, hb5 = hi.y, hb6 = hi.z, hb7 = hi.w;
#pragma unroll
      for (int j = 0; j < 4; j++) {
        const float w = Wreg[j][i];
        acc[j][0] += w * hb0; acc[j][1] += w * hb1;
        acc[j][2] += w * hb2; acc[j][3] += w * hb3;
        acc[j][4] += w * hb4; acc[j][5] += w * hb5;
        acc[j][6] += w * hb6; acc[j][7] += w * hb7;
      }
    }

    // write K-partials: output idx = (batch col)*16 + (h row), h fastest
#pragma unroll
    for (int j = 0; j < 4; j++)
#pragma unroll
      for (int b = 0; b < 8; b++)
        red[kq * RED_STRIDE + (tb * 8 + b) * 16 + th * 4 + j] = acc[j][b];
    __syncthreads();

    // reduce 32 partials + fused epilogue
    float s = 0.0f;
#pragma unroll
    for (int q = 0; q < 32; q++) s += red[q * RED_STRIDE + tid];
    const size_t oidx =
        (size_t)t * BB * NHID + (size_t)(b0 + o_b) * NHID + hblk + o_h;
    const float u = __ldcg(&g_xin[oidx]);
    out[oidx] = tanhf(s + u);

    // grid barrier: all 128 blocks finish step t before any reads out[t]
    __syncthreads();
    __threadfence();
    if (tid == 0) {
      atomicAdd(&g_bar, 1u);
      const unsigned int target = 128u * (unsigned)(t + 1);
      while (*((volatile unsigned int*)&g_bar) < target) {
        __nanosleep(32);
      }
    }
    __threadfence();
    __syncthreads();
  }
}

// ---------------------------------------------------------------------------
extern "C" void kernel_launch(void* const* d_in, const int* in_sizes, int n_in,
                              void* d_out, int out_size) {
  const float* x     = (const float*)d_in[0];  // (T,B,NIN) f32
  const float* h0    = (const float*)d_in[1];  // (B,NH)    f32
  const float* w_rec = (const float*)d_in[2];  // (NH, NH+NIN+1) f32
  float* out = (float*)d_out;                  // (T,B,NH)  f32

  const int pre_smem = (64 * 132 + 128 * 68 + 64) * (int)sizeof(float);      // 68864 B
  const int rec_smem = (512 * HS_STRIDE + 32 * RED_STRIDE) * (int)sizeof(float); // 107008 B
  cudaFuncSetAttribute(precompute_kernel,
                       cudaFuncAttributeMaxDynamicSharedMemorySize, pre_smem);
  cudaFuncSetAttribute(rnn_rec_kernel,
                       cudaFuncAttributeMaxDynamicSharedMemorySize, rec_smem);

  zero_bar_kernel<<<1, 1>>>();

  dim3 pgrid(TT * BB / 64, NHID / 64);  // 1024 x 8
  precompute_kernel<<<pgrid, 256, pre_smem>>>(x, w_rec);

  rnn_rec_kernel<<<128, 256, rec_smem>>>(h0, w_rec, out);
}